// round 3
// baseline (speedup 1.0000x reference)
#include <cuda_runtime.h>

#define CIN   64
#define PW    38            // padded width (32 + 2*3)
#define NPIX  1024          // 32*32
#define NPAD  (PW*PW)       // 1444

#define PLANES_BYTES (4*NPAD*16)                     // ktA,ktB,vtA,vtB = 92416
#define SMEM_BYTES   (PLANES_BYTES + 1536*4 + 224)   // + wt + rels = 98784

typedef unsigned long long ull;

__device__ __forceinline__ ull ffma2(ull a, ull b, ull c) {
    ull d;
    asm("fma.rn.f32x2 %0, %1, %2, %3;" : "=l"(d) : "l"(a), "l"(b), "l"(c));
    return d;
}
__device__ __forceinline__ ull mul2(ull a, ull b) {
    ull d;
    asm("mul.rn.f32x2 %0, %1, %2;" : "=l"(d) : "l"(a), "l"(b));
    return d;
}
__device__ __forceinline__ ull pk2(float a, float b) {
    ull r;
    asm("mov.b64 %0, {%1, %2};" : "=l"(r) : "f"(a), "f"(b));
    return r;
}
__device__ __forceinline__ float2 upk2(ull v) {
    float2 t;
    asm("mov.b64 {%0, %1}, %2;" : "=f"(t.x), "=f"(t.y) : "l"(v));
    return t;
}

// One CTA per (batch b, group g). 256 threads, 2 CTAs/SM (independent phase
// progression — P1 fma-heavy overlaps P2 lds-heavy across CTAs).
// Each thread owns a column of 4 output rows.
// Phase 1: project q/k/v (f32x2 FMA), q -> regs (pre-scaled by log2e), k/v -> smem.
// Phase 2: R=4 row-blocked 7x7 local attention, exp2-based softmax + ring mask.
template<bool ISH>
__global__ __launch_bounds__(256, 2)
void attn_conv_fused(const float* __restrict__ x,
                     const float* __restrict__ wq,
                     const float* __restrict__ wk,
                     const float* __restrict__ wv,
                     const float* __restrict__ rel,   // relh (ISH) or relw
                     const float* __restrict__ cval,
                     float* __restrict__ out,
                     int gbase)
{
    extern __shared__ char smem[];
    ulonglong2* ktA = (ulonglong2*)smem;
    ulonglong2* ktB = ktA + NPAD;
    ulonglong2* vtA = ktB + NPAD;
    ulonglong2* vtB = vtA + NPAD;
    float* wt   = (float*)(smem + PLANES_BYTES);     // [64 ci][24]
    float* rels = wt + 1536;                         // [7][8]

    const int gl  = blockIdx.x;        // 0..3 within class
    const int g   = gbase + gl;
    const int b   = blockIdx.y;
    const int tid = threadIdx.x;
    const int wr  = tid >> 5;          // warp 0..7
    const int w   = tid & 31;          // column
    const int h0  = wr * 4;            // first of 4 owned rows

    // ---- stage weights (transposed ci-major) ----
    for (int idx = tid; idx < 1536; idx += 256) {
        int ci = idx / 24, c = idx % 24;
        float v;
        if (c < 8)       v = wq[(g*8 + c)        * 64 + ci];
        else if (c < 16) v = wk[(g*8 + (c - 8))  * 64 + ci];
        else             v = wv[(g*8 + (c - 16)) * 64 + ci];
        wt[idx] = v;
    }
    if (tid < 56) {
        int i = tid >> 3, c = tid & 7;
        rels[tid] = rel[(gl*8 + c)*7 + i];
    }
    // zero padded k/v planes (borders act as zero padding)
    {
        ulonglong2 z; z.x = 0ULL; z.y = 0ULL;
        for (int idx = tid; idx < 4*NPAD; idx += 256) ((ulonglong2*)smem)[idx] = z;
    }
    __syncthreads();

    const ulonglong2* relp = (const ulonglong2*)rels;  // [7][2]
    const ull l2e2 = pk2(1.4426950408889634f, 1.4426950408889634f);

    // ---- Phase 1: projection for the 4 owned pixels (2 passes of 2 rows) ----
    ull   Q[4][4];       // q (pre-scaled by log2e), 8 ch packed
    float bias[4][7];    // (q . rel) * log2e
    const float* xb = x + (size_t)b * CIN * NPIX;

    #pragma unroll
    for (int pass = 0; pass < 2; pass++) {
        const int r0 = h0 + 2*pass;
        ull acc[2][12];
        #pragma unroll
        for (int e = 0; e < 2; e++)
            #pragma unroll
            for (int p = 0; p < 12; p++) acc[e][p] = 0ULL;

        #pragma unroll 4
        for (int ci = 0; ci < 64; ci++) {
            float x0 = xb[ci*NPIX + r0*32 + w];
            float x1 = xb[ci*NPIX + (r0+1)*32 + w];
            ull xp0 = pk2(x0, x0);
            ull xp1 = pk2(x1, x1);
            const ulonglong2* wrow = (const ulonglong2*)(wt + ci*24);
            #pragma unroll
            for (int p = 0; p < 6; p++) {
                ulonglong2 wv2 = wrow[p];
                acc[0][2*p]   = ffma2(xp0, wv2.x, acc[0][2*p]);
                acc[0][2*p+1] = ffma2(xp0, wv2.y, acc[0][2*p+1]);
                acc[1][2*p]   = ffma2(xp1, wv2.x, acc[1][2*p]);
                acc[1][2*p+1] = ffma2(xp1, wv2.y, acc[1][2*p+1]);
            }
        }
        #pragma unroll
        for (int e = 0; e < 2; e++) {
            const int o = 2*pass + e;
            // scale q by log2e so phase 2 can use exp2 directly
            Q[o][0] = mul2(acc[e][0], l2e2); Q[o][1] = mul2(acc[e][1], l2e2);
            Q[o][2] = mul2(acc[e][2], l2e2); Q[o][3] = mul2(acc[e][3], l2e2);
            #pragma unroll
            for (int i = 0; i < 7; i++) {
                ulonglong2 r01 = relp[i*2], r23 = relp[i*2 + 1];
                ull d = ffma2(Q[o][0], r01.x,
                        ffma2(Q[o][1], r01.y,
                        ffma2(Q[o][2], r23.x,
                        ffma2(Q[o][3], r23.y, 0ULL))));
                float2 df = upk2(d);
                bias[o][i] = df.x + df.y;
            }
            const int pi = (h0 + o + 3)*PW + (w + 3);
            ulonglong2 tkv;
            tkv.x = acc[e][4];  tkv.y = acc[e][5];  ktA[pi] = tkv;
            tkv.x = acc[e][6];  tkv.y = acc[e][7];  ktB[pi] = tkv;
            tkv.x = acc[e][8];  tkv.y = acc[e][9];  vtA[pi] = tkv;
            tkv.x = acc[e][10]; tkv.y = acc[e][11]; vtB[pi] = tkv;
        }
    }
    __syncthreads();

    // ---- Phase 2: row-blocked attention (4 outputs share window rows) ----
    float Z[4] = {0.f, 0.f, 0.f, 0.f};
    ull aa[4][4];
    #pragma unroll
    for (int o = 0; o < 4; o++)
        #pragma unroll
        for (int p = 0; p < 4; p++) aa[o][p] = 0ULL;

    #pragma unroll
    for (int pr = 0; pr < 10; pr++) {         // padded window rows h0..h0+9
        const int rowoff = (h0 + pr)*PW + w;
        #pragma unroll
        for (int j = 0; j < 7; j++) {
            const int off = rowoff + j;
            ulonglong2 ka = ktA[off], kb = ktB[off];
            ulonglong2 va = vtA[off], vb = vtB[off];
            #pragma unroll
            for (int o = 0; o < 4; o++) {
                const int i = pr - o;          // tap row for output o
                if (i >= 0 && i < 7) {
                    ull s2 = ffma2(Q[o][0], ka.x,
                             ffma2(Q[o][1], ka.y,
                             ffma2(Q[o][2], kb.x,
                             ffma2(Q[o][3], kb.y, 0ULL))));
                    float2 sf = upk2(s2);
                    float s = sf.x + sf.y + bias[o][ISH ? i : j];
                    float e = exp2f(s);        // max-free softmax, log2 domain
                    Z[o] += e;
                    ull e2 = pk2(e, e);
                    aa[o][0] = ffma2(e2, va.x, aa[o][0]);
                    aa[o][1] = ffma2(e2, va.y, aa[o][1]);
                    aa[o][2] = ffma2(e2, vb.x, aa[o][2]);
                    aa[o][3] = ffma2(e2, vb.y, aa[o][3]);
                }
            }
        }
    }

    // ---- epilogue: adaptive ring mask + normalize + store ----
    const float cvg = cval[g];
    float* outbase = out + ((size_t)b * 64 + g * 8) * NPIX;
    #pragma unroll
    for (int o = 0; o < 4; o++) {
        const int h   = h0 + o;
        const int pos = h*32 + w;
        int r  = min(h, 31 - h);
        int lo = (h <= 31 - h) ? r : r + 1;
        int hi = 31 - r;
        float omv  = fminf(fmaxf(((float)(r - 15) + cvg*16.0f)*(1.0f/3.0f) + 1.0f,
                                 0.0f), 1.0f);
        float mval = (w >= lo && w <= hi) ? omv : 1.0f;
        float sc   = __fdividef(mval, Z[o]);

        float2 o01 = upk2(aa[o][0]), o23 = upk2(aa[o][1]);
        float2 o45 = upk2(aa[o][2]), o67 = upk2(aa[o][3]);
        outbase[0*NPIX + pos] = o01.x * sc;
        outbase[1*NPIX + pos] = o01.y * sc;
        outbase[2*NPIX + pos] = o23.x * sc;
        outbase[3*NPIX + pos] = o23.y * sc;
        outbase[4*NPIX + pos] = o45.x * sc;
        outbase[5*NPIX + pos] = o45.y * sc;
        outbase[6*NPIX + pos] = o67.x * sc;
        outbase[7*NPIX + pos] = o67.y * sc;
    }
}

extern "C" void kernel_launch(void* const* d_in, const int* in_sizes, int n_in,
                              void* d_out, int out_size)
{
    const float* x    = (const float*)d_in[0];
    const float* wq   = (const float*)d_in[1];
    const float* wk   = (const float*)d_in[2];
    const float* wv   = (const float*)d_in[3];
    const float* relh = (const float*)d_in[4];
    const float* relw = (const float*)d_in[5];
    const float* cv   = (const float*)d_in[6];
    float* out = (float*)d_out;

    cudaFuncSetAttribute(attn_conv_fused<true>,
                         cudaFuncAttributeMaxDynamicSharedMemorySize, SMEM_BYTES);
    cudaFuncSetAttribute(attn_conv_fused<false>,
                         cudaFuncAttributeMaxDynamicSharedMemorySize, SMEM_BYTES);
    attn_conv_fused<true ><<<dim3(4, 32), 256, SMEM_BYTES>>>(x, wq, wk, wv, relh, cv, out, 0);
    attn_conv_fused<false><<<dim3(4, 32), 256, SMEM_BYTES>>>(x, wq, wk, wv, relw, cv, out, 4);
}

// round 4
// speedup vs baseline: 1.2192x; 1.2192x over previous
#include <cuda_runtime.h>

#define CIN   64
#define PW    38            // padded width (32 + 2*3)
#define NPIX  1024          // 32*32
#define NPAD  (PW*PW)       // 1444

#define PLANES_BYTES (4*NPAD*16)                     // ktA,ktB,vtA,vtB = 92416
#define SMEM_BYTES   (PLANES_BYTES + 1536*4 + 224)   // + wt + rels = 98784

typedef unsigned long long ull;

__device__ __forceinline__ ull ffma2(ull a, ull b, ull c) {
    ull d;
    asm("fma.rn.f32x2 %0, %1, %2, %3;" : "=l"(d) : "l"(a), "l"(b), "l"(c));
    return d;
}
__device__ __forceinline__ ull mul2(ull a, ull b) {
    ull d;
    asm("mul.rn.f32x2 %0, %1, %2;" : "=l"(d) : "l"(a), "l"(b));
    return d;
}
__device__ __forceinline__ ull pk2(float a, float b) {
    ull r;
    asm("mov.b64 %0, {%1, %2};" : "=l"(r) : "f"(a), "f"(b));
    return r;
}
__device__ __forceinline__ float2 upk2(ull v) {
    float2 t;
    asm("mov.b64 {%0, %1}, %2;" : "=f"(t.x), "=f"(t.y) : "l"(v));
    return t;
}

// One CTA per (batch b, group g). 256 threads, 2 CTAs/SM resident.
// Independent CTA barriers let fma-heavy phase 1 of one CTA overlap the
// LDS/MUFU-heavy phase 2 of its co-resident CTA.
// Each thread owns a column of 4 output rows.
// Phase 1: project q/k/v (f32x2 FMA), q -> regs (pre-scaled by log2e), k/v -> smem.
// Phase 2: R=4 row-blocked 7x7 local attention, exp2-based softmax + ring mask.
__global__ __launch_bounds__(256, 2)
void attn_conv_fused(const float* __restrict__ x,
                     const float* __restrict__ wq,
                     const float* __restrict__ wk,
                     const float* __restrict__ wv,
                     const float* __restrict__ relh,
                     const float* __restrict__ relw,
                     const float* __restrict__ cval,
                     float* __restrict__ out)
{
    extern __shared__ char smem[];
    ulonglong2* ktA = (ulonglong2*)smem;
    ulonglong2* ktB = ktA + NPAD;
    ulonglong2* vtA = ktB + NPAD;
    ulonglong2* vtB = vtA + NPAD;
    float* wt   = (float*)(smem + PLANES_BYTES);     // [64 ci][24]
    float* rels = wt + 1536;                         // [7][8]

    const int g   = blockIdx.x;        // 0..7
    const int b   = blockIdx.y;
    const int tid = threadIdx.x;
    const int wr  = tid >> 5;          // warp 0..7
    const int w   = tid & 31;          // column
    const int h0  = wr * 4;            // first of 4 owned rows
    const bool isH = (g < 4);

    // ---- stage weights (transposed ci-major) ----
    for (int idx = tid; idx < 1536; idx += 256) {
        int ci = idx / 24, c = idx % 24;
        float v;
        if (c < 8)       v = wq[(g*8 + c)        * 64 + ci];
        else if (c < 16) v = wk[(g*8 + (c - 8))  * 64 + ci];
        else             v = wv[(g*8 + (c - 16)) * 64 + ci];
        wt[idx] = v;
    }
    if (tid < 56) {
        int i = tid >> 3, c = tid & 7;
        rels[tid] = isH ? relh[(g*8 + c)*7 + i]
                        : relw[((g - 4)*8 + c)*7 + i];
    }
    // zero padded k/v planes (borders act as zero padding)
    {
        ulonglong2 z; z.x = 0ULL; z.y = 0ULL;
        for (int idx = tid; idx < 4*NPAD; idx += 256) ((ulonglong2*)smem)[idx] = z;
    }
    __syncthreads();

    const ulonglong2* relp = (const ulonglong2*)rels;  // [7][2]
    const ull l2e2 = pk2(1.4426950408889634f, 1.4426950408889634f);

    // ---- Phase 1: projection for the 4 owned pixels (2 passes of 2 rows) ----
    ull   Q[4][4];       // q (pre-scaled by log2e), 8 ch packed
    float bias[4][7];    // (q . rel) * log2e
    const float* xb = x + (size_t)b * CIN * NPIX;

    #pragma unroll
    for (int pass = 0; pass < 2; pass++) {
        const int r0 = h0 + 2*pass;
        ull acc[2][12];
        #pragma unroll
        for (int e = 0; e < 2; e++)
            #pragma unroll
            for (int p = 0; p < 12; p++) acc[e][p] = 0ULL;

        #pragma unroll 4
        for (int ci = 0; ci < 64; ci++) {
            float x0 = xb[ci*NPIX + r0*32 + w];
            float x1 = xb[ci*NPIX + (r0+1)*32 + w];
            ull xp0 = pk2(x0, x0);
            ull xp1 = pk2(x1, x1);
            const ulonglong2* wrow = (const ulonglong2*)(wt + ci*24);
            #pragma unroll
            for (int p = 0; p < 6; p++) {
                ulonglong2 wv2 = wrow[p];
                acc[0][2*p]   = ffma2(xp0, wv2.x, acc[0][2*p]);
                acc[0][2*p+1] = ffma2(xp0, wv2.y, acc[0][2*p+1]);
                acc[1][2*p]   = ffma2(xp1, wv2.x, acc[1][2*p]);
                acc[1][2*p+1] = ffma2(xp1, wv2.y, acc[1][2*p+1]);
            }
        }
        #pragma unroll
        for (int e = 0; e < 2; e++) {
            const int o = 2*pass + e;
            // scale q by log2e so phase 2 can use exp2 directly
            Q[o][0] = mul2(acc[e][0], l2e2); Q[o][1] = mul2(acc[e][1], l2e2);
            Q[o][2] = mul2(acc[e][2], l2e2); Q[o][3] = mul2(acc[e][3], l2e2);
            #pragma unroll
            for (int i = 0; i < 7; i++) {
                ulonglong2 r01 = relp[i*2], r23 = relp[i*2 + 1];
                ull d = ffma2(Q[o][0], r01.x,
                        ffma2(Q[o][1], r01.y,
                        ffma2(Q[o][2], r23.x,
                        ffma2(Q[o][3], r23.y, 0ULL))));
                float2 df = upk2(d);
                bias[o][i] = df.x + df.y;
            }
            const int pi = (h0 + o + 3)*PW + (w + 3);
            ulonglong2 tkv;
            tkv.x = acc[e][4];  tkv.y = acc[e][5];  ktA[pi] = tkv;
            tkv.x = acc[e][6];  tkv.y = acc[e][7];  ktB[pi] = tkv;
            tkv.x = acc[e][8];  tkv.y = acc[e][9];  vtA[pi] = tkv;
            tkv.x = acc[e][10]; tkv.y = acc[e][11]; vtB[pi] = tkv;
        }
    }
    __syncthreads();

    // ---- Phase 2: row-blocked attention (4 outputs share window rows) ----
    float Z[4] = {0.f, 0.f, 0.f, 0.f};
    ull aa[4][4];
    #pragma unroll
    for (int o = 0; o < 4; o++)
        #pragma unroll
        for (int p = 0; p < 4; p++) aa[o][p] = 0ULL;

    #pragma unroll
    for (int pr = 0; pr < 10; pr++) {         // padded window rows h0..h0+9
        const int rowoff = (h0 + pr)*PW + w;
        #pragma unroll
        for (int j = 0; j < 7; j++) {
            const int off = rowoff + j;
            ulonglong2 ka = ktA[off], kb = ktB[off];
            ulonglong2 va = vtA[off], vb = vtB[off];
            #pragma unroll
            for (int o = 0; o < 4; o++) {
                const int i = pr - o;          // tap row for output o
                if (i >= 0 && i < 7) {
                    ull s2 = ffma2(Q[o][0], ka.x,
                             ffma2(Q[o][1], ka.y,
                             ffma2(Q[o][2], kb.x,
                             ffma2(Q[o][3], kb.y, 0ULL))));
                    float2 sf = upk2(s2);
                    float s = sf.x + sf.y + (isH ? bias[o][i] : bias[o][j]);
                    float e = exp2f(s);        // max-free softmax, log2 domain
                    Z[o] += e;
                    ull e2 = pk2(e, e);
                    aa[o][0] = ffma2(e2, va.x, aa[o][0]);
                    aa[o][1] = ffma2(e2, va.y, aa[o][1]);
                    aa[o][2] = ffma2(e2, vb.x, aa[o][2]);
                    aa[o][3] = ffma2(e2, vb.y, aa[o][3]);
                }
            }
        }
    }

    // ---- epilogue: adaptive ring mask + normalize + store ----
    const float cvg = cval[g];
    float* outbase = out + ((size_t)b * 64 + g * 8) * NPIX;
    #pragma unroll
    for (int o = 0; o < 4; o++) {
        const int h   = h0 + o;
        const int pos = h*32 + w;
        int r  = min(h, 31 - h);
        int lo = (h <= 31 - h) ? r : r + 1;
        int hi = 31 - r;
        float omv  = fminf(fmaxf(((float)(r - 15) + cvg*16.0f)*(1.0f/3.0f) + 1.0f,
                                 0.0f), 1.0f);
        float mval = (w >= lo && w <= hi) ? omv : 1.0f;
        float sc   = __fdividef(mval, Z[o]);

        float2 o01 = upk2(aa[o][0]), o23 = upk2(aa[o][1]);
        float2 o45 = upk2(aa[o][2]), o67 = upk2(aa[o][3]);
        outbase[0*NPIX + pos] = o01.x * sc;
        outbase[1*NPIX + pos] = o01.y * sc;
        outbase[2*NPIX + pos] = o23.x * sc;
        outbase[3*NPIX + pos] = o23.y * sc;
        outbase[4*NPIX + pos] = o45.x * sc;
        outbase[5*NPIX + pos] = o45.y * sc;
        outbase[6*NPIX + pos] = o67.x * sc;
        outbase[7*NPIX + pos] = o67.y * sc;
    }
}

extern "C" void kernel_launch(void* const* d_in, const int* in_sizes, int n_in,
                              void* d_out, int out_size)
{
    const float* x    = (const float*)d_in[0];
    const float* wq   = (const float*)d_in[1];
    const float* wk   = (const float*)d_in[2];
    const float* wv   = (const float*)d_in[3];
    const float* relh = (const float*)d_in[4];
    const float* relw = (const float*)d_in[5];
    const float* cv   = (const float*)d_in[6];
    float* out = (float*)d_out;

    cudaFuncSetAttribute(attn_conv_fused,
                         cudaFuncAttributeMaxDynamicSharedMemorySize, SMEM_BYTES);
    attn_conv_fused<<<dim3(8, 32), 256, SMEM_BYTES>>>(x, wq, wk, wv, relh, relw, cv, out);
}

// round 6
// speedup vs baseline: 1.2843x; 1.0534x over previous
#include <cuda_runtime.h>

#define CIN   64
#define PW    38            // padded width (32 + 2*3)
#define NPIX  1024          // 32*32
#define NPAD  (PW*PW)       // 1444

#define PLANES_BYTES (4*NPAD*16)                     // ktA,ktB,vtA,vtB = 92416
#define SMEM_BYTES   (PLANES_BYTES + 1536*4 + 224)   // + wt + rels = 98784

typedef unsigned long long ull;

__device__ __forceinline__ ull ffma2(ull a, ull b, ull c) {
    ull d;
    asm("fma.rn.f32x2 %0, %1, %2, %3;" : "=l"(d) : "l"(a), "l"(b), "l"(c));
    return d;
}
__device__ __forceinline__ ull mul2(ull a, ull b) {
    ull d;
    asm("mul.rn.f32x2 %0, %1, %2;" : "=l"(d) : "l"(a), "l"(b));
    return d;
}
__device__ __forceinline__ ull pk2(float a, float b) {
    ull r;
    asm("mov.b64 %0, {%1, %2};" : "=l"(r) : "f"(a), "f"(b));
    return r;
}
__device__ __forceinline__ float2 upk2(ull v) {
    float2 t;
    asm("mov.b64 {%0, %1}, %2;" : "=f"(t.x), "=f"(t.y) : "l"(v));
    return t;
}
__device__ __forceinline__ float ex2(float s) {
    float r;
    asm("ex2.approx.ftz.f32 %0, %1;" : "=f"(r) : "f"(s));
    return r;
}

// Phase 2 specialized on group class (isH uniform per CTA): no per-tap selects,
// bias folded into the FFMA2 c-seed (hoisted per-pr for ISH).
template<bool ISH>
__device__ __forceinline__ void phase2_run(
    const ulonglong2* __restrict__ ktA, const ulonglong2* __restrict__ ktB,
    const ulonglong2* __restrict__ vtA, const ulonglong2* __restrict__ vtB,
    const ull (&Q)[4][4], const float (&bias)[4][7],
    float (&Z)[4], ull (&aa)[4][4], int h0, int w)
{
    #pragma unroll
    for (int pr = 0; pr < 10; pr++) {         // padded window rows h0..h0+9
        const int rowoff = (h0 + pr)*PW + w;
        ull seed[4];
        if (ISH) {
            #pragma unroll
            for (int o = 0; o < 4; o++) {
                const int i = pr - o;
                if (i >= 0 && i < 7) seed[o] = pk2(bias[o][i], 0.f);
            }
        }
        #pragma unroll
        for (int j = 0; j < 7; j++) {
            const int off = rowoff + j;
            ulonglong2 ka = ktA[off], kb = ktB[off];
            float e[4];
            #pragma unroll
            for (int o = 0; o < 4; o++) {
                const int i = pr - o;          // tap row for output o
                if (i >= 0 && i < 7) {
                    ull c0 = ISH ? seed[o] : pk2(bias[o][j], 0.f);
                    ull s2 = ffma2(Q[o][0], ka.x,
                             ffma2(Q[o][1], ka.y,
                             ffma2(Q[o][2], kb.x,
                             ffma2(Q[o][3], kb.y, c0))));
                    float2 sf = upk2(s2);
                    e[o] = ex2(sf.x + sf.y);   // max-free softmax, log2 domain
                    Z[o] += e[o];
                }
            }
            ulonglong2 va = vtA[off], vb = vtB[off];
            #pragma unroll
            for (int o = 0; o < 4; o++) {
                const int i = pr - o;
                if (i >= 0 && i < 7) {
                    ull e2 = pk2(e[o], e[o]);
                    aa[o][0] = ffma2(e2, va.x, aa[o][0]);
                    aa[o][1] = ffma2(e2, va.y, aa[o][1]);
                    aa[o][2] = ffma2(e2, vb.x, aa[o][2]);
                    aa[o][3] = ffma2(e2, vb.y, aa[o][3]);
                }
            }
        }
    }
}

// One CTA per (batch b, group g). 256 threads, 2 CTAs/SM resident.
// Each thread owns a column of 4 output rows.
// Phase 1: project q/k/v (f32x2 FMA), q -> regs (pre-scaled by log2e), k/v -> smem.
// Phase 2: R=4 row-blocked 7x7 local attention, exp2-based softmax + ring mask.
__global__ __launch_bounds__(256, 2)
void attn_conv_fused(const float* __restrict__ x,
                     const float* __restrict__ wq,
                     const float* __restrict__ wk,
                     const float* __restrict__ wv,
                     const float* __restrict__ relh,
                     const float* __restrict__ relw,
                     const float* __restrict__ cval,
                     float* __restrict__ out)
{
    extern __shared__ char smem[];
    ulonglong2* ktA = (ulonglong2*)smem;
    ulonglong2* ktB = ktA + NPAD;
    ulonglong2* vtA = ktB + NPAD;
    ulonglong2* vtB = vtA + NPAD;
    float* wt   = (float*)(smem + PLANES_BYTES);     // [64 ci][24]
    float* rels = wt + 1536;                         // [7][8]

    const int g   = blockIdx.x;        // 0..7
    const int b   = blockIdx.y;
    const int tid = threadIdx.x;
    const int wr  = tid >> 5;          // warp 0..7
    const int w   = tid & 31;          // column
    const int h0  = wr * 4;            // first of 4 owned rows
    const bool isH = (g < 4);
    const float cvg = cval[g];         // load early, used only in epilogue

    // ---- stage weights (transposed ci-major) ----
    for (int idx = tid; idx < 1536; idx += 256) {
        int ci = idx / 24, c = idx % 24;
        float v;
        if (c < 8)       v = wq[(g*8 + c)        * 64 + ci];
        else if (c < 16) v = wk[(g*8 + (c - 8))  * 64 + ci];
        else             v = wv[(g*8 + (c - 16)) * 64 + ci];
        wt[idx] = v;
    }
    if (tid < 56) {
        int i = tid >> 3, c = tid & 7;
        rels[tid] = isH ? relh[(g*8 + c)*7 + i]
                        : relw[((g - 4)*8 + c)*7 + i];
    }
    // zero padded k/v planes (borders act as zero padding)
    {
        ulonglong2 z; z.x = 0ULL; z.y = 0ULL;
        for (int idx = tid; idx < 4*NPAD; idx += 256) ((ulonglong2*)smem)[idx] = z;
    }
    __syncthreads();

    const ulonglong2* relp = (const ulonglong2*)rels;  // [7][2]
    const ull l2e2 = pk2(1.4426950408889634f, 1.4426950408889634f);

    // ---- Phase 1: projection for the 4 owned pixels (2 passes of 2 rows) ----
    ull   Q[4][4];       // q (pre-scaled by log2e), 8 ch packed
    float bias[4][7];    // (q . rel) * log2e
    const float* xb = x + (size_t)b * CIN * NPIX;

    #pragma unroll
    for (int pass = 0; pass < 2; pass++) {
        const int r0 = h0 + 2*pass;
        ull acc[2][12];
        #pragma unroll
        for (int e = 0; e < 2; e++)
            #pragma unroll
            for (int p = 0; p < 12; p++) acc[e][p] = 0ULL;

        #pragma unroll 8
        for (int ci = 0; ci < 64; ci++) {
            float x0 = xb[ci*NPIX + r0*32 + w];
            float x1 = xb[ci*NPIX + (r0+1)*32 + w];
            ull xp0 = pk2(x0, x0);
            ull xp1 = pk2(x1, x1);
            const ulonglong2* wrow = (const ulonglong2*)(wt + ci*24);
            #pragma unroll
            for (int p = 0; p < 6; p++) {
                ulonglong2 wv2 = wrow[p];
                acc[0][2*p]   = ffma2(xp0, wv2.x, acc[0][2*p]);
                acc[0][2*p+1] = ffma2(xp0, wv2.y, acc[0][2*p+1]);
                acc[1][2*p]   = ffma2(xp1, wv2.x, acc[1][2*p]);
                acc[1][2*p+1] = ffma2(xp1, wv2.y, acc[1][2*p+1]);
            }
        }
        #pragma unroll
        for (int e = 0; e < 2; e++) {
            const int o = 2*pass + e;
            // scale q by log2e so phase 2 can use exp2 directly
            Q[o][0] = mul2(acc[e][0], l2e2); Q[o][1] = mul2(acc[e][1], l2e2);
            Q[o][2] = mul2(acc[e][2], l2e2); Q[o][3] = mul2(acc[e][3], l2e2);
            #pragma unroll
            for (int i = 0; i < 7; i++) {
                ulonglong2 r01 = relp[i*2], r23 = relp[i*2 + 1];
                ull d = ffma2(Q[o][0], r01.x,
                        ffma2(Q[o][1], r01.y,
                        ffma2(Q[o][2], r23.x,
                        ffma2(Q[o][3], r23.y, 0ULL))));
                float2 df = upk2(d);
                bias[o][i] = df.x + df.y;
            }
            const int pi = (h0 + o + 3)*PW + (w + 3);
            ulonglong2 tkv;
            tkv.x = acc[e][4];  tkv.y = acc[e][5];  ktA[pi] = tkv;
            tkv.x = acc[e][6];  tkv.y = acc[e][7];  ktB[pi] = tkv;
            tkv.x = acc[e][8];  tkv.y = acc[e][9];  vtA[pi] = tkv;
            tkv.x = acc[e][10]; tkv.y = acc[e][11]; vtB[pi] = tkv;
        }
    }
    __syncthreads();

    // ---- Phase 2 ----
    float Z[4] = {0.f, 0.f, 0.f, 0.f};
    ull aa[4][4];
    #pragma unroll
    for (int o = 0; o < 4; o++)
        #pragma unroll
        for (int p = 0; p < 4; p++) aa[o][p] = 0ULL;

    if (isH) phase2_run<true >(ktA, ktB, vtA, vtB, Q, bias, Z, aa, h0, w);
    else     phase2_run<false>(ktA, ktB, vtA, vtB, Q, bias, Z, aa, h0, w);

    // ---- epilogue: adaptive ring mask + normalize + store ----
    float* outbase = out + ((size_t)b * 64 + g * 8) * NPIX;
    #pragma unroll
    for (int o = 0; o < 4; o++) {
        const int h   = h0 + o;
        const int pos = h*32 + w;
        int r  = min(h, 31 - h);
        int lo = (h <= 31 - h) ? r : r + 1;
        int hi = 31 - r;
        float omv  = fminf(fmaxf(((float)(r - 15) + cvg*16.0f)*(1.0f/3.0f) + 1.0f,
                                 0.0f), 1.0f);
        float mval = (w >= lo && w <= hi) ? omv : 1.0f;
        float sc   = __fdividef(mval, Z[o]);

        float2 o01 = upk2(aa[o][0]), o23 = upk2(aa[o][1]);
        float2 o45 = upk2(aa[o][2]), o67 = upk2(aa[o][3]);
        outbase[0*NPIX + pos] = o01.x * sc;
        outbase[1*NPIX + pos] = o01.y * sc;
        outbase[2*NPIX + pos] = o23.x * sc;
        outbase[3*NPIX + pos] = o23.y * sc;
        outbase[4*NPIX + pos] = o45.x * sc;
        outbase[5*NPIX + pos] = o45.y * sc;
        outbase[6*NPIX + pos] = o67.x * sc;
        outbase[7*NPIX + pos] = o67.y * sc;
    }
}

extern "C" void kernel_launch(void* const* d_in, const int* in_sizes, int n_in,
                              void* d_out, int out_size)
{
    const float* x    = (const float*)d_in[0];
    const float* wq   = (const float*)d_in[1];
    const float* wk   = (const float*)d_in[2];
    const float* wv   = (const float*)d_in[3];
    const float* relh = (const float*)d_in[4];
    const float* relw = (const float*)d_in[5];
    const float* cv   = (const float*)d_in[6];
    float* out = (float*)d_out;

    cudaFuncSetAttribute(attn_conv_fused,
                         cudaFuncAttributeMaxDynamicSharedMemorySize, SMEM_BYTES);
    attn_conv_fused<<<dim3(8, 32), 256, SMEM_BYTES>>>(x, wq, wk, wv, relh, relw, cv, out);
}